// round 1
// baseline (speedup 1.0000x reference)
#include <cuda_runtime.h>

#define NPTS 32768
#define GRIDSZ 16
#define CDIM 64
#define PPB 8                 // points per block
#define TPB (PPB * 16)        // 16 threads per point, each owns 4 output channels

__global__ void __launch_bounds__(TPB) resample_dense_kernel(
    const int*   __restrict__ pidx,
    const float* __restrict__ pos,
    const float* __restrict__ xs,
    const float* __restrict__ K,     // [4,16,16,16,64,64]
    const float* __restrict__ B,     // [4,16,16,16,64]
    float*       __restrict__ out)   // [N,64]
{
    __shared__ float sx[PPB][CDIM];

    const int lp = threadIdx.x >> 4;   // local point 0..7
    const int q  = threadIdx.x & 15;   // float4 quad 0..15
    const int p  = blockIdx.x * PPB + lp;

    // stage xs for this point (float4 coalesced)
    float4 xv = reinterpret_cast<const float4*>(xs + (size_t)p * CDIM)[q];
    reinterpret_cast<float4*>(sx[lp])[q] = xv;

    // per-point scalars (redundant across the 16 threads; cheap, broadcast loads)
    const int k  = pidx[p];
    const float px = pos[p * 3 + 0] * GRIDSZ - 0.5f;
    const float py = pos[p * 3 + 1] * GRIDSZ - 0.5f;
    const float pz = pos[p * 3 + 2] * GRIDSZ - 0.5f;
    const float fx = floorf(px), fy = floorf(py), fz = floorf(pz);

    float wx[2], wy[2], wz[2];
    wx[1] = px - fx; wx[0] = 1.0f - wx[1];
    wy[1] = py - fy; wy[0] = 1.0f - wy[1];
    wz[1] = pz - fz; wz[0] = 1.0f - wz[1];

    int ix[2], iy[2], iz[2];
    ix[0] = min(max((int)fx,     0), GRIDSZ - 1);
    ix[1] = min(max((int)fx + 1, 0), GRIDSZ - 1);
    iy[0] = min(max((int)fy,     0), GRIDSZ - 1);
    iy[1] = min(max((int)fy + 1, 0), GRIDSZ - 1);
    iz[0] = min(max((int)fz,     0), GRIDSZ - 1);
    iz[1] = min(max((int)fz + 1, 0), GRIDSZ - 1);

    __syncthreads();

    float4 acc = make_float4(0.f, 0.f, 0.f, 0.f);

    #pragma unroll
    for (int cz = 0; cz < 2; ++cz) {
        #pragma unroll
        for (int cy = 0; cy < 2; ++cy) {
            #pragma unroll
            for (int cx = 0; cx < 2; ++cx) {
                const float w = wz[cz] * wy[cy] * wx[cx];
                const int vtx = ((k * GRIDSZ + iz[cz]) * GRIDSZ + iy[cy]) * GRIDSZ + ix[cx];

                const float4* Mq =
                    reinterpret_cast<const float4*>(K + (size_t)vtx * CDIM * CDIM) + q;

                float4 s = make_float4(0.f, 0.f, 0.f, 0.f);
                #pragma unroll 16
                for (int c = 0; c < CDIM; ++c) {
                    const float xc = sx[lp][c];
                    const float4 m = Mq[c * (CDIM / 4)];
                    s.x = fmaf(xc, m.x, s.x);
                    s.y = fmaf(xc, m.y, s.y);
                    s.z = fmaf(xc, m.z, s.z);
                    s.w = fmaf(xc, m.w, s.w);
                }

                const float4 b =
                    reinterpret_cast<const float4*>(B + (size_t)vtx * CDIM)[q];

                acc.x = fmaf(w, s.x + b.x, acc.x);
                acc.y = fmaf(w, s.y + b.y, acc.y);
                acc.z = fmaf(w, s.z + b.z, acc.z);
                acc.w = fmaf(w, s.w + b.w, acc.w);
            }
        }
    }

    reinterpret_cast<float4*>(out + (size_t)p * CDIM)[q] = acc;
}

extern "C" void kernel_launch(void* const* d_in, const int* in_sizes, int n_in,
                              void* d_out, int out_size)
{
    const int*   pidx = (const int*)  d_in[0];  // param_idxs (N,1) int32
    const float* pos  = (const float*)d_in[1];  // pos (N,3)
    const float* xs   = (const float*)d_in[2];  // xs (N,64)
    const float* K    = (const float*)d_in[3];  // kernels (4,16,16,16,64,64)
    const float* B    = (const float*)d_in[4];  // biases (4,16,16,16,64)
    float*       out  = (float*)d_out;          // (N,64)

    resample_dense_kernel<<<NPTS / PPB, TPB>>>(pidx, pos, xs, K, B, out);
}

// round 2
// speedup vs baseline: 2.4942x; 2.4942x over previous
#include <cuda_runtime.h>

#define NPTS   32768
#define GRIDSZ 16
#define CDIM   64
#define NVERT  (4 * GRIDSZ * GRIDSZ * GRIDSZ)   // 16384
#define CAP    256

// scratch (static device globals — allocation-free)
__device__ int  g_cnt[NVERT];
__device__ int2 g_list[NVERT * CAP];            // (point_id, weight bits)

__global__ void zero_counts_kernel() {
    int i = blockIdx.x * blockDim.x + threadIdx.x;
    if (i < NVERT) g_cnt[i] = 0;
}

__global__ void bin_points_kernel(const int* __restrict__ pidx,
                                  const float* __restrict__ pos)
{
    int p = blockIdx.x * blockDim.x + threadIdx.x;
    if (p >= NPTS) return;

    const int k  = pidx[p];
    const float px = pos[p * 3 + 0] * GRIDSZ - 0.5f;
    const float py = pos[p * 3 + 1] * GRIDSZ - 0.5f;
    const float pz = pos[p * 3 + 2] * GRIDSZ - 0.5f;
    const float fx = floorf(px), fy = floorf(py), fz = floorf(pz);

    float wx[2], wy[2], wz[2];
    wx[1] = px - fx; wx[0] = 1.0f - wx[1];
    wy[1] = py - fy; wy[0] = 1.0f - wy[1];
    wz[1] = pz - fz; wz[0] = 1.0f - wz[1];

    int ix[2], iy[2], iz[2];
    ix[0] = min(max((int)fx,     0), GRIDSZ - 1);
    ix[1] = min(max((int)fx + 1, 0), GRIDSZ - 1);
    iy[0] = min(max((int)fy,     0), GRIDSZ - 1);
    iy[1] = min(max((int)fy + 1, 0), GRIDSZ - 1);
    iz[0] = min(max((int)fz,     0), GRIDSZ - 1);
    iz[1] = min(max((int)fz + 1, 0), GRIDSZ - 1);

    #pragma unroll
    for (int cz = 0; cz < 2; ++cz)
        #pragma unroll
        for (int cy = 0; cy < 2; ++cy)
            #pragma unroll
            for (int cx = 0; cx < 2; ++cx) {
                const float w = wz[cz] * wy[cy] * wx[cx];
                const int v = ((k * GRIDSZ + iz[cz]) * GRIDSZ + iy[cy]) * GRIDSZ + ix[cx];
                int slot = atomicAdd(&g_cnt[v], 1);
                if (slot < CAP)
                    g_list[v * CAP + slot] = make_int2(p, __float_as_int(w));
            }
}

#define GTPB 128

__global__ void __launch_bounds__(GTPB) gather_kernel(
    const float* __restrict__ K,     // [NVERT][64][64]
    const float* __restrict__ B,     // [NVERT][64]
    const float* __restrict__ xs,    // [N][64]
    float*       __restrict__ out)   // [N][64]
{
    __shared__ float4 sM[CDIM * 16];     // [c*16 + q] = K[c][4q..4q+3]
    __shared__ float  sX[16][CDIM];      // 16 staged points
    __shared__ int    sPid[16];
    __shared__ float  sW[16];

    const int v = blockIdx.x;
    int cnt = g_cnt[v];
    if (cnt > CAP) cnt = CAP;
    if (cnt == 0) return;

    const int tid = threadIdx.x;
    const int q = tid & 15;      // channel quad (4 output channels)
    const int g = tid >> 4;      // point slot 0..7 (handles slots g and g+8)

    // matrix -> smem (read exactly once chip-wide)
    const float4* Kf4 = reinterpret_cast<const float4*>(K + (size_t)v * CDIM * CDIM);
    #pragma unroll
    for (int i = 0; i < 8; ++i) sM[tid + i * GTPB] = Kf4[tid + i * GTPB];

    const float4 bq = reinterpret_cast<const float4*>(B + (size_t)v * CDIM)[q];

    for (int base = 0; base < cnt; base += 16) {
        __syncthreads();   // prev chunk compute done / sM ready on first iter

        if (tid < 16) {
            const int s = base + tid;
            int pid = 0; float w = 0.0f;
            if (s < cnt) {
                const int2 e = g_list[v * CAP + s];
                pid = e.x; w = __int_as_float(e.y);
            }
            sPid[tid] = pid; sW[tid] = w;
        }
        __syncthreads();

        // stage xs for both of this thread's points (float4 coalesced)
        {
            const int p0 = sPid[g], p1 = sPid[g + 8];
            reinterpret_cast<float4*>(sX[g])[q] =
                reinterpret_cast<const float4*>(xs + (size_t)p0 * CDIM)[q];
            reinterpret_cast<float4*>(sX[g + 8])[q] =
                reinterpret_cast<const float4*>(xs + (size_t)p1 * CDIM)[q];
        }
        __syncthreads();

        float4 a0 = make_float4(0.f, 0.f, 0.f, 0.f);
        float4 a1 = make_float4(0.f, 0.f, 0.f, 0.f);

        #pragma unroll
        for (int c4 = 0; c4 < 16; ++c4) {
            const float4 x0 = reinterpret_cast<const float4*>(sX[g])[c4];
            const float4 x1 = reinterpret_cast<const float4*>(sX[g + 8])[c4];
            const float4 m0 = sM[(4 * c4 + 0) * 16 + q];
            const float4 m1 = sM[(4 * c4 + 1) * 16 + q];
            const float4 m2 = sM[(4 * c4 + 2) * 16 + q];
            const float4 m3 = sM[(4 * c4 + 3) * 16 + q];

            a0.x = fmaf(x0.x, m0.x, a0.x); a0.y = fmaf(x0.x, m0.y, a0.y);
            a0.z = fmaf(x0.x, m0.z, a0.z); a0.w = fmaf(x0.x, m0.w, a0.w);
            a0.x = fmaf(x0.y, m1.x, a0.x); a0.y = fmaf(x0.y, m1.y, a0.y);
            a0.z = fmaf(x0.y, m1.z, a0.z); a0.w = fmaf(x0.y, m1.w, a0.w);
            a0.x = fmaf(x0.z, m2.x, a0.x); a0.y = fmaf(x0.z, m2.y, a0.y);
            a0.z = fmaf(x0.z, m2.z, a0.z); a0.w = fmaf(x0.z, m2.w, a0.w);
            a0.x = fmaf(x0.w, m3.x, a0.x); a0.y = fmaf(x0.w, m3.y, a0.y);
            a0.z = fmaf(x0.w, m3.z, a0.z); a0.w = fmaf(x0.w, m3.w, a0.w);

            a1.x = fmaf(x1.x, m0.x, a1.x); a1.y = fmaf(x1.x, m0.y, a1.y);
            a1.z = fmaf(x1.x, m0.z, a1.z); a1.w = fmaf(x1.x, m0.w, a1.w);
            a1.x = fmaf(x1.y, m1.x, a1.x); a1.y = fmaf(x1.y, m1.y, a1.y);
            a1.z = fmaf(x1.y, m1.z, a1.z); a1.w = fmaf(x1.y, m1.w, a1.w);
            a1.x = fmaf(x1.z, m2.x, a1.x); a1.y = fmaf(x1.z, m2.y, a1.y);
            a1.z = fmaf(x1.z, m2.z, a1.z); a1.w = fmaf(x1.z, m2.w, a1.w);
            a1.x = fmaf(x1.w, m3.x, a1.x); a1.y = fmaf(x1.w, m3.y, a1.y);
            a1.z = fmaf(x1.w, m3.z, a1.z); a1.w = fmaf(x1.w, m3.w, a1.w);
        }

        // out += w * (x@M + b)
        if (base + g < cnt) {
            const float w = sW[g];
            float* o = out + (size_t)sPid[g] * CDIM + 4 * q;
            atomicAdd(o + 0, w * (a0.x + bq.x));
            atomicAdd(o + 1, w * (a0.y + bq.y));
            atomicAdd(o + 2, w * (a0.z + bq.z));
            atomicAdd(o + 3, w * (a0.w + bq.w));
        }
        if (base + 8 + g < cnt) {
            const float w = sW[g + 8];
            float* o = out + (size_t)sPid[g + 8] * CDIM + 4 * q;
            atomicAdd(o + 0, w * (a1.x + bq.x));
            atomicAdd(o + 1, w * (a1.y + bq.y));
            atomicAdd(o + 2, w * (a1.z + bq.z));
            atomicAdd(o + 3, w * (a1.w + bq.w));
        }
    }
}

extern "C" void kernel_launch(void* const* d_in, const int* in_sizes, int n_in,
                              void* d_out, int out_size)
{
    const int*   pidx = (const int*)  d_in[0];
    const float* pos  = (const float*)d_in[1];
    const float* xs   = (const float*)d_in[2];
    const float* K    = (const float*)d_in[3];
    const float* B    = (const float*)d_in[4];
    float*       out  = (float*)d_out;

    zero_counts_kernel<<<(NVERT + 255) / 256, 256>>>();
    bin_points_kernel<<<(NPTS + 127) / 128, 128>>>(pidx, pos);
    cudaMemsetAsync(d_out, 0, (size_t)out_size * sizeof(float));
    gather_kernel<<<NVERT, GTPB>>>(K, B, xs, out);
}

// round 3
// speedup vs baseline: 2.6982x; 1.0818x over previous
#include <cuda_runtime.h>

#define NPTS   32768
#define GRIDSZ 16
#define CDIM   64
#define NVERT  (4 * GRIDSZ * GRIDSZ * GRIDSZ)   // 16384
#define CAP    256

__device__ int  g_cnt[NVERT];
__device__ int2 g_list[NVERT * CAP];            // (point_id, weight bits)

__global__ void zero_counts_kernel() {
    int i = blockIdx.x * blockDim.x + threadIdx.x;
    if (i < NVERT) g_cnt[i] = 0;
}

__global__ void bin_points_kernel(const int* __restrict__ pidx,
                                  const float* __restrict__ pos)
{
    int p = blockIdx.x * blockDim.x + threadIdx.x;
    if (p >= NPTS) return;

    const int k  = pidx[p];
    const float px = pos[p * 3 + 0] * GRIDSZ - 0.5f;
    const float py = pos[p * 3 + 1] * GRIDSZ - 0.5f;
    const float pz = pos[p * 3 + 2] * GRIDSZ - 0.5f;
    const float fx = floorf(px), fy = floorf(py), fz = floorf(pz);

    float wx[2], wy[2], wz[2];
    wx[1] = px - fx; wx[0] = 1.0f - wx[1];
    wy[1] = py - fy; wy[0] = 1.0f - wy[1];
    wz[1] = pz - fz; wz[0] = 1.0f - wz[1];

    int ix[2], iy[2], iz[2];
    ix[0] = min(max((int)fx,     0), GRIDSZ - 1);
    ix[1] = min(max((int)fx + 1, 0), GRIDSZ - 1);
    iy[0] = min(max((int)fy,     0), GRIDSZ - 1);
    iy[1] = min(max((int)fy + 1, 0), GRIDSZ - 1);
    iz[0] = min(max((int)fz,     0), GRIDSZ - 1);
    iz[1] = min(max((int)fz + 1, 0), GRIDSZ - 1);

    #pragma unroll
    for (int cz = 0; cz < 2; ++cz)
        #pragma unroll
        for (int cy = 0; cy < 2; ++cy)
            #pragma unroll
            for (int cx = 0; cx < 2; ++cx) {
                const float w = wz[cz] * wy[cy] * wx[cx];
                const int v = ((k * GRIDSZ + iz[cz]) * GRIDSZ + iy[cy]) * GRIDSZ + ix[cx];
                int slot = atomicAdd(&g_cnt[v], 1);
                if (slot < CAP)
                    g_list[v * CAP + slot] = make_int2(p, __float_as_int(w));
            }
}

#define GTPB 128

__device__ __forceinline__ void red_add_v4(float* o, float4 v) {
    asm volatile("red.global.add.v4.f32 [%0], {%1,%2,%3,%4};"
                 :: "l"(o), "f"(v.x), "f"(v.y), "f"(v.z), "f"(v.w) : "memory");
}

__device__ __forceinline__ void fma4x4(float4& a, float4 x,
                                       float4 m0, float4 m1, float4 m2, float4 m3)
{
    a.x = fmaf(x.x, m0.x, a.x); a.y = fmaf(x.x, m0.y, a.y);
    a.z = fmaf(x.x, m0.z, a.z); a.w = fmaf(x.x, m0.w, a.w);
    a.x = fmaf(x.y, m1.x, a.x); a.y = fmaf(x.y, m1.y, a.y);
    a.z = fmaf(x.y, m1.z, a.z); a.w = fmaf(x.y, m1.w, a.w);
    a.x = fmaf(x.z, m2.x, a.x); a.y = fmaf(x.z, m2.y, a.y);
    a.z = fmaf(x.z, m2.z, a.z); a.w = fmaf(x.z, m2.w, a.w);
    a.x = fmaf(x.w, m3.x, a.x); a.y = fmaf(x.w, m3.y, a.y);
    a.z = fmaf(x.w, m3.z, a.z); a.w = fmaf(x.w, m3.w, a.w);
}

__global__ void __launch_bounds__(GTPB) gather_kernel(
    const float* __restrict__ K,     // [NVERT][64][64]
    const float* __restrict__ B,     // [NVERT][64]
    const float* __restrict__ xs,    // [N][64]
    float*       __restrict__ out)   // [N][64]
{
    __shared__ float4 sM[CDIM * 16];     // [c*16 + q] = K[c][4q..4q+3]
    __shared__ float  sX[16][CDIM];
    __shared__ int    sPid[16];
    __shared__ float  sW[16];

    const int v = blockIdx.x;
    int cnt = g_cnt[v];
    if (cnt > CAP) cnt = CAP;
    if (cnt == 0) return;

    const int tid = threadIdx.x;
    const int q = tid & 15;      // channel quad (4 output channels)
    const int g = tid >> 4;      // point slot 0..7 (slots g and g+8)

    const float4* Kf4 = reinterpret_cast<const float4*>(K + (size_t)v * CDIM * CDIM);
    #pragma unroll
    for (int i = 0; i < 8; ++i) sM[tid + i * GTPB] = Kf4[tid + i * GTPB];

    const float4 bq = reinterpret_cast<const float4*>(B + (size_t)v * CDIM)[q];

    for (int base = 0; base < cnt; base += 16) {
        __syncthreads();

        if (tid < 16) {
            const int s = base + tid;
            int pid = 0; float w = 0.0f;
            if (s < cnt) {
                const int2 e = g_list[v * CAP + s];
                pid = e.x; w = __int_as_float(e.y);
            }
            sPid[tid] = pid; sW[tid] = w;
        }
        __syncthreads();

        const bool two = (base + 8 < cnt);   // block-uniform

        {
            const int p0 = sPid[g];
            reinterpret_cast<float4*>(sX[g])[q] =
                reinterpret_cast<const float4*>(xs + (size_t)p0 * CDIM)[q];
            if (two) {
                const int p1 = sPid[g + 8];
                reinterpret_cast<float4*>(sX[g + 8])[q] =
                    reinterpret_cast<const float4*>(xs + (size_t)p1 * CDIM)[q];
            }
        }
        __syncthreads();

        float4 a0 = make_float4(0.f, 0.f, 0.f, 0.f);
        float4 a1 = make_float4(0.f, 0.f, 0.f, 0.f);

        if (two) {
            #pragma unroll
            for (int c4 = 0; c4 < 16; ++c4) {
                const float4 x0 = reinterpret_cast<const float4*>(sX[g])[c4];
                const float4 x1 = reinterpret_cast<const float4*>(sX[g + 8])[c4];
                const float4 m0 = sM[(4 * c4 + 0) * 16 + q];
                const float4 m1 = sM[(4 * c4 + 1) * 16 + q];
                const float4 m2 = sM[(4 * c4 + 2) * 16 + q];
                const float4 m3 = sM[(4 * c4 + 3) * 16 + q];
                fma4x4(a0, x0, m0, m1, m2, m3);
                fma4x4(a1, x1, m0, m1, m2, m3);
            }
        } else {
            #pragma unroll
            for (int c4 = 0; c4 < 16; ++c4) {
                const float4 x0 = reinterpret_cast<const float4*>(sX[g])[c4];
                const float4 m0 = sM[(4 * c4 + 0) * 16 + q];
                const float4 m1 = sM[(4 * c4 + 1) * 16 + q];
                const float4 m2 = sM[(4 * c4 + 2) * 16 + q];
                const float4 m3 = sM[(4 * c4 + 3) * 16 + q];
                fma4x4(a0, x0, m0, m1, m2, m3);
            }
        }

        if (base + g < cnt) {
            const float w = sW[g];
            float* o = out + (size_t)sPid[g] * CDIM + 4 * q;
            red_add_v4(o, make_float4(w * (a0.x + bq.x), w * (a0.y + bq.y),
                                      w * (a0.z + bq.z), w * (a0.w + bq.w)));
        }
        if (two && (base + 8 + g < cnt)) {
            const float w = sW[g + 8];
            float* o = out + (size_t)sPid[g + 8] * CDIM + 4 * q;
            red_add_v4(o, make_float4(w * (a1.x + bq.x), w * (a1.y + bq.y),
                                      w * (a1.z + bq.z), w * (a1.w + bq.w)));
        }
    }
}

extern "C" void kernel_launch(void* const* d_in, const int* in_sizes, int n_in,
                              void* d_out, int out_size)
{
    const int*   pidx = (const int*)  d_in[0];
    const float* pos  = (const float*)d_in[1];
    const float* xs   = (const float*)d_in[2];
    const float* K    = (const float*)d_in[3];
    const float* B    = (const float*)d_in[4];
    float*       out  = (float*)d_out;

    zero_counts_kernel<<<(NVERT + 255) / 256, 256>>>();
    bin_points_kernel<<<(NPTS + 127) / 128, 128>>>(pidx, pos);
    cudaMemsetAsync(d_out, 0, (size_t)out_size * sizeof(float));
    gather_kernel<<<NVERT, GTPB>>>(K, B, xs, out);
}